// round 3
// baseline (speedup 1.0000x reference)
#include <cuda_runtime.h>

// LIF spike recurrence, T=8:
//   mem = mem*TAU + x[t]*alpha; spike = (mem > Vth); mem = spike ? 0 : mem
//
// Persistent grid-stride kernel: grid sized to the chip (NUM_CTAS fixed),
// each thread walks float4 "columns" of the spatial dim. Per column: 8
// front-batched LDG.128 (MLP=8), register recurrence, 8 STG.128.
// Loads use streaming hint (zero reuse); stores use default policy so L2
// absorbs the write burst.

#define TAU 0.5f
#define NUM_CTAS 1216   /* 152 SMs x 8 CTAs */
#define THREADS  256

__global__ void __launch_bounds__(THREADS) lif_spike_kernel(
    const float* __restrict__ x,
    const float* __restrict__ alpha_p,
    const float* __restrict__ vth_p,
    float* __restrict__ out,
    int ncols /* spatial / 4 */,
    int spatial)
{
    const float alpha = __ldg(alpha_p);
    const float vth   = __ldg(vth_p);

    const int stride = NUM_CTAS * THREADS;

    for (int col = blockIdx.x * THREADS + threadIdx.x; col < ncols;
         col += stride) {
        const int i4 = col * 4;

        // ── Front-batch all 8 timestep loads (8 independent LDG.128) ──
        float4 xt[8];
        #pragma unroll
        for (int t = 0; t < 8; t++) {
            xt[t] = __ldcs(reinterpret_cast<const float4*>(
                x + (size_t)t * (size_t)spatial + i4));
        }

        // ── Recurrence + stores ──
        float m0 = 0.f, m1 = 0.f, m2 = 0.f, m3 = 0.f;
        #pragma unroll
        for (int t = 0; t < 8; t++) {
            m0 = m0 * TAU + xt[t].x * alpha;
            m1 = m1 * TAU + xt[t].y * alpha;
            m2 = m2 * TAU + xt[t].z * alpha;
            m3 = m3 * TAU + xt[t].w * alpha;

            float4 s;
            s.x = (m0 > vth) ? 1.f : 0.f;
            s.y = (m1 > vth) ? 1.f : 0.f;
            s.z = (m2 > vth) ? 1.f : 0.f;
            s.w = (m3 > vth) ? 1.f : 0.f;

            m0 = (m0 > vth) ? 0.f : m0;
            m1 = (m1 > vth) ? 0.f : m1;
            m2 = (m2 > vth) ? 0.f : m2;
            m3 = (m3 > vth) ? 0.f : m3;

            *reinterpret_cast<float4*>(
                out + (size_t)t * (size_t)spatial + i4) = s;
        }
    }
}

extern "C" void kernel_launch(void* const* d_in, const int* in_sizes, int n_in,
                              void* d_out, int out_size) {
    const float* x     = (const float*)d_in[0];
    const float* alpha = (const float*)d_in[1];
    const float* vth   = (const float*)d_in[2];
    float* out = (float*)d_out;

    const int total   = in_sizes[0];     // T * spatial
    const int spatial = total / 8;       // T = 8
    const int ncols   = spatial / 4;     // float4 columns (spatial % 4 == 0)

    lif_spike_kernel<<<NUM_CTAS, THREADS>>>(x, alpha, vth, out, ncols, spatial);
}